// round 12
// baseline (speedup 1.0000x reference)
#include <cuda_runtime.h>
#include <cuda_fp16.h>
#include <cstdint>

#define H 256
#define NA 100000
#define NB 250000
#define NM 2000
#define AF 133
#define BF 147
#define MAXNB 6

#define MT_B 1954          // ceil(250000/128)
#define MT_A 782           // ceil(100000/128)
#define KP0 192
#define KP1 256
#define KP2 448

typedef long long ll;
typedef unsigned int uint;
typedef unsigned short ushort;
typedef unsigned long long ull;

// ---------------- device scratch (allocation-guard-safe) ----------------
__device__ float  g_inp[(ll)NB * H];
__device__ float  g_msg0[(ll)NB * H];   // iter2 output
__device__ float  g_msg1[(ll)NB * H];   // iter1 output / atom_hidden scratch
__device__ float  g_amsg[(ll)NA * H];
__device__ ushort g_wi_hi[256 * KP0], g_wi_lo[256 * KP0];
__device__ ushort g_wh_hi[256 * KP1], g_wh_lo[256 * KP1];
__device__ ushort g_wo_hi[256 * KP2], g_wo_lo[256 * KP2];
__device__ float  g_molsum[NM * H];
__device__ float  g_wsum[NM];

// ---------------- helpers ----------------
__device__ __forceinline__ uint smem_u32(const void* p) {
    uint a;
    asm("{ .reg .u64 t; cvta.to.shared.u64 t, %1; cvt.u32.u64 %0, t; }" : "=r"(a) : "l"(p));
    return a;
}
__device__ __forceinline__ uint h2pack(float a, float b) {   // fp16 rn pair, a in low
    __half2 t = __floats2half2_rn(a, b);
    return *(uint*)&t;
}
__device__ __forceinline__ void ldsm4(uint* r, uint addr) {
    asm volatile("ldmatrix.sync.aligned.m8n8.x4.shared.b16 {%0,%1,%2,%3}, [%4];"
                 : "=r"(r[0]), "=r"(r[1]), "=r"(r[2]), "=r"(r[3]) : "r"(addr));
}
__device__ __forceinline__ void mma16816(float* d, const uint* a, const uint* b) {
    asm volatile(
        "mma.sync.aligned.m16n8k16.row.col.f32.f16.f16.f32 "
        "{%0,%1,%2,%3}, {%4,%5,%6,%7}, {%8,%9}, {%0,%1,%2,%3};"
        : "+f"(d[0]), "+f"(d[1]), "+f"(d[2]), "+f"(d[3])
        : "r"(a[0]), "r"(a[1]), "r"(a[2]), "r"(a[3]), "r"(b[0]), "r"(b[1]));
}
__device__ __forceinline__ void cp16(uint dst, const void* src) {
    asm volatile("cp.async.ca.shared.global [%0], [%1], 16;" :: "r"(dst), "l"(src));
}
__device__ __forceinline__ void cp_commit() {
    asm volatile("cp.async.commit_group;" ::: "memory");
}
__device__ __forceinline__ void cp_wait0() {
    asm volatile("cp.async.wait_group 0;" ::: "memory");
}

// SMEM: 2 buffers x 3 planes (A, Bh, Bl) x (128 rows x 40 fp16, 80B stride)
#define PLNB 10240
#define BUFB (3 * PLNB)          // 30720
#define SMEM_TOTAL (2 * BUFB)    // 61440

struct TArgs {
    const float* A;                      // mode0: f_bonds
    const ushort *w_hi, *w_lo;           // pre-split fp16 weights [256 x KPAD], k-contig
    const float *amsg, *msgc;            // mode1 gather sources / mode2 amsg
    const int *b2a, *b2revb;
    const float* inp;                    // mode1 epilogue add
    const float* fatoms;                 // mode2
    float *inp_out, *msg_out;            // outputs (mode2: msg_out = hidden scratch)
    const float *b_o, *w_atoms;          // mode2
    int M;
};

template <int MODE>
__global__ __launch_bounds__(256, 1) void hgemm(TArgs g) {
    constexpr int KPAD = (MODE == 0) ? KP0 : ((MODE == 1) ? KP1 : KP2);
    constexpr int KT   = KPAD / 32;
    constexpr int KSRC = (MODE == 0) ? BF : ((MODE == 1) ? H : (AF + H));

    extern __shared__ char smem[];
    const uint sb = smem_u32(smem);

    const int tid = threadIdx.x;
    const int lane = tid & 31, wid = tid >> 5;
    const int wr = wid >> 1, wc = wid & 1;
    const int bm = blockIdx.x * 128;
    const int bn = blockIdx.y * 128;

    // loader geometry: thread -> (row2, k-half)
    const int row2 = tid >> 1, half = tid & 1;
    const int growl = bm + row2;
    const bool rv = growl < g.M;
    const float *p1 = nullptr, *p2 = nullptr;
    if (MODE == 1 && rv) {
        p1 = g.amsg + (ll)g.b2a[growl] * H;
        p2 = g.msgc + (ll)g.b2revb[growl] * H;
    }
    const ushort* wg_hi = g.w_hi + (ll)(bn + row2) * KPAD;
    const ushort* wg_lo = g.w_lo + (ll)(bn + row2) * KPAD;

    // ldmatrix lane addresses (buffer-relative)
    const int a_row = (lane & 7) + ((lane >> 3) & 1) * 8;
    const int a_k   = (lane >> 4) * 8;
    const uint offA = ((uint)((wr * 32 + a_row) * 40 + a_k) << 1);
    const int b_n = (lane & 7) + (lane >> 4) * 8;
    const int b_k = ((lane >> 3) & 1) * 8;
    const uint offB = PLNB + ((uint)((wc * 64 + b_n) * 40 + b_k) << 1);

    float acc[2][8][4];
#pragma unroll
    for (int mi = 0; mi < 2; mi++)
#pragma unroll
        for (int ni = 0; ni < 8; ni++)
#pragma unroll
            for (int q = 0; q < 4; q++) acc[mi][ni][q] = 0.f;

    float pv[16];

    auto prefetchA = [&](int c) {
        const int kbase = c * 32 + half * 16;
        if (MODE == 1) {
#pragma unroll
            for (int i = 0; i < 4; i++) {
                float4 x = rv ? *(const float4*)(p1 + kbase + i * 4) : make_float4(0, 0, 0, 0);
                float4 y = rv ? *(const float4*)(p2 + kbase + i * 4) : make_float4(0, 0, 0, 0);
                // relu-on-read of reverse message (idempotent on iter-2 input)
                pv[4 * i + 0] = x.x - fmaxf(y.x, 0.f);
                pv[4 * i + 1] = x.y - fmaxf(y.y, 0.f);
                pv[4 * i + 2] = x.z - fmaxf(y.z, 0.f);
                pv[4 * i + 3] = x.w - fmaxf(y.w, 0.f);
            }
        } else {
#pragma unroll
            for (int t = 0; t < 16; t++) {
                int k = kbase + t;
                float v = 0.f;
                if (rv && k < KSRC) {
                    if (MODE == 0) v = __ldg(&g.A[(ll)growl * BF + k]);
                    else v = (k < AF) ? __ldg(&g.fatoms[(ll)growl * AF + k])
                                      : __ldg(&g.amsg[(ll)growl * H + (k - AF)]);
                }
                pv[t] = v;
            }
        }
    };
    auto cpB = [&](int c, int s) {
        const int kbase = c * 32 + half * 16;
        const uint dst = sb + (uint)s * BUFB + (uint)(row2 * 80 + half * 32);
        cp16(dst + PLNB,          wg_hi + kbase);
        cp16(dst + PLNB + 16,     wg_hi + kbase + 8);
        cp16(dst + 2 * PLNB,      wg_lo + kbase);
        cp16(dst + 2 * PLNB + 16, wg_lo + kbase + 8);
    };
    auto stsA = [&](int s) {
        char* base = smem + (size_t)s * BUFB;
        uint ao = (uint)(row2 * 40 + half * 16);
        uint4 v0 = make_uint4(h2pack(pv[0], pv[1]), h2pack(pv[2], pv[3]),
                              h2pack(pv[4], pv[5]), h2pack(pv[6], pv[7]));
        uint4 v1 = make_uint4(h2pack(pv[8], pv[9]), h2pack(pv[10], pv[11]),
                              h2pack(pv[12], pv[13]), h2pack(pv[14], pv[15]));
        *(uint4*)(base + (ao << 1))       = v0;
        *(uint4*)(base + ((ao + 8) << 1)) = v1;
    };

    // prologue: fill buffer 0
    prefetchA(0);
    cpB(0, 0);
    cp_commit();
    stsA(0);
    cp_wait0();
    __syncthreads();

    for (int c = 0; c < KT; c++) {
        const int s = c & 1, ns = s ^ 1;
        if (c + 1 < KT) { prefetchA(c + 1); cpB(c + 1, ns); }
        cp_commit();

        // ---- compute chunk c from buffer s: 2 MMAs per (mi,nt,sub) ----
        const uint bufo = sb + (uint)s * BUFB;
#pragma unroll
        for (int ks = 0; ks < 2; ks++) {
            const uint kb2 = (uint)(ks * 32);
            uint Ah[2][4], Bh[4][4], Bl[4][4];
#pragma unroll
            for (int mi = 0; mi < 2; mi++)
                ldsm4(Ah[mi], bufo + offA + kb2 + mi * 1280);
#pragma unroll
            for (int nt = 0; nt < 4; nt++) {
                ldsm4(Bh[nt], bufo + offB + kb2 + nt * 1280);
                ldsm4(Bl[nt], bufo + offB + PLNB + kb2 + nt * 1280);
            }
#pragma unroll
            for (int mi = 0; mi < 2; mi++)
#pragma unroll
                for (int nt = 0; nt < 4; nt++)
#pragma unroll
                    for (int sub = 0; sub < 2; sub++) {
                        const int ni = nt * 2 + sub;
                        mma16816(acc[mi][ni], Ah[mi], &Bh[nt][sub * 2]);
                        mma16816(acc[mi][ni], Ah[mi], &Bl[nt][sub * 2]);
                    }
        }

        if (c + 1 < KT) stsA(ns);
        cp_wait0();
        __syncthreads();
    }

    // ---------------- epilogue ----------------
    const int grp = lane >> 2, qi = lane & 3;
#pragma unroll
    for (int mi = 0; mi < 2; mi++) {
        const int r0 = bm + wr * 32 + mi * 16 + grp;
        const int r1 = r0 + 8;
        float w0 = 0.f, w1 = 0.f;
        if (MODE == 2) {
            w0 = (r0 < g.M) ? __ldg(&g.w_atoms[r0]) : 0.f;
            w1 = (r1 < g.M) ? __ldg(&g.w_atoms[r1]) : 0.f;
        }
#pragma unroll
        for (int ni = 0; ni < 8; ni++) {
            const int col = bn + wc * 64 + ni * 8 + qi * 2;
            float c0 = acc[mi][ni][0], c1 = acc[mi][ni][1];
            float c2 = acc[mi][ni][2], c3 = acc[mi][ni][3];
            if (MODE == 0) {
                if (r0 < g.M) *(float2*)&g.inp_out[(ll)r0 * H + col] = make_float2(c0, c1);
                if (r1 < g.M) *(float2*)&g.inp_out[(ll)r1 * H + col] = make_float2(c2, c3);
            } else if (MODE == 1) {
                if (r0 < g.M) {
                    float2 iv = *(const float2*)&g.inp[(ll)r0 * H + col];
                    *(float2*)&g.msg_out[(ll)r0 * H + col] =
                        make_float2(fmaxf(c0 + iv.x, 0.f), fmaxf(c1 + iv.y, 0.f));
                }
                if (r1 < g.M) {
                    float2 iv = *(const float2*)&g.inp[(ll)r1 * H + col];
                    *(float2*)&g.msg_out[(ll)r1 * H + col] =
                        make_float2(fmaxf(c2 + iv.x, 0.f), fmaxf(c3 + iv.y, 0.f));
                }
            } else {
                float2 bo = *(const float2*)&g.b_o[col];
                if (r0 < g.M)
                    *(float2*)&g.msg_out[(ll)r0 * H + col] =
                        make_float2(fmaxf(c0 + bo.x, 0.f) * w0, fmaxf(c1 + bo.y, 0.f) * w0);
                if (r1 < g.M)
                    *(float2*)&g.msg_out[(ll)r1 * H + col] =
                        make_float2(fmaxf(c2 + bo.x, 0.f) * w1, fmaxf(c3 + bo.y, 0.f) * w1);
            }
        }
    }
}

// ---------------- weight prepack: [K x 256] fp32 -> [256 x Kpad] fp16 hi/lo ----
__global__ void prepack_w(const float* __restrict__ src, ushort* __restrict__ hi,
                          ushort* __restrict__ lo, int K, int Kpad) {
    int idx = blockIdx.x * 256 + threadIdx.x;
    if (idx >= 256 * Kpad) return;
    int n = idx / Kpad, k = idx - n * Kpad;
    float v = (k < K) ? src[(ll)k * 256 + n] : 0.f;
    __half h = __float2half_rn(v);
    hi[idx] = *(ushort*)&h;
    __half l = __float2half_rn(v - __half2float(h));
    lo[idx] = *(ushort*)&l;
}

// ---------------- small kernels ----------------
__global__ __launch_bounds__(256) void gather_kernel(const float* __restrict__ msg,
                                                     const float* __restrict__ w_bonds,
                                                     const int* __restrict__ a2b,
                                                     float* __restrict__ amsg) {
    int tid = threadIdx.x;
    int a = blockIdx.x * 4 + (tid >> 6);
    int lane = tid & 63;
    float4 s = make_float4(0.f, 0.f, 0.f, 0.f);
#pragma unroll
    for (int j = 0; j < MAXNB; j++) {
        int b = a2b[a * MAXNB + j];
        float w = w_bonds[b];
        float4 mv = *(const float4*)&msg[(ll)b * H + lane * 4];
        s.x += w * fmaxf(mv.x, 0.f); s.y += w * fmaxf(mv.y, 0.f);
        s.z += w * fmaxf(mv.z, 0.f); s.w += w * fmaxf(mv.w, 0.f);
    }
    *(float4*)&amsg[(ll)a * H + lane * 4] = s;
}

__global__ void zero_kernel(float* molsum, float* wsum) {
    int i = blockIdx.x * 256 + threadIdx.x;
    if (i < NM * H) molsum[i] = 0.f;
    if (i < NM) wsum[i] = 0.f;
}
__global__ void wsum_kernel(const float* __restrict__ w_atoms, const int* __restrict__ mol_ids,
                            float* __restrict__ wsum) {
    int i = blockIdx.x * 256 + threadIdx.x;
    if (i < NA) atomicAdd(&wsum[mol_ids[i]], w_atoms[i]);
}

__global__ __launch_bounds__(256) void segreduce_kernel(const float* __restrict__ hid,
                                                        const int* __restrict__ mol_ids,
                                                        float* __restrict__ molsum) {
    int col = blockIdx.y * 128 + (threadIdx.x & 127);
    int rbase = blockIdx.x * 128 + (threadIdx.x >> 7) * 64;
    if (rbase >= NA) return;
    int rend = rbase + 64; if (rend > NA) rend = NA;
    int cur = -1; float s = 0.f;
    for (int r = rbase; r < rend; r++) {
        int m = __ldg(&mol_ids[r]);
        float v = hid[(ll)r * H + col];
        if (m != cur) {
            if (cur >= 0) atomicAdd(&molsum[(ll)cur * H + col], s);
            cur = m; s = 0.f;
        }
        s += v;
    }
    if (cur >= 0) atomicAdd(&molsum[(ll)cur * H + col], s);
}

__global__ void finalize_kernel(const float* __restrict__ molsum, const float* __restrict__ wsum,
                                const float* __restrict__ deg, float* __restrict__ out) {
    int m = blockIdx.x, hc = threadIdx.x;
    float w = wsum[m];
    float v = (w > 0.f) ? molsum[m * H + hc] / w : 0.f;
    out[m * H + hc] = deg[m] * v;
}

extern "C" void kernel_launch(void* const* d_in, const int* in_sizes, int n_in,
                              void* d_out, int out_size) {
    const float* f_atoms = (const float*)d_in[0];
    const float* f_bonds = (const float*)d_in[1];
    const float* w_atoms = (const float*)d_in[2];
    const float* w_bonds = (const float*)d_in[3];
    const float* W_i = (const float*)d_in[4];
    const float* W_h = (const float*)d_in[5];
    const float* W_o = (const float*)d_in[6];
    const float* b_o = (const float*)d_in[7];
    const float* deg = (const float*)d_in[8];
    const int* a2b = (const int*)d_in[9];
    const int* b2a = (const int*)d_in[10];
    const int* b2revb = (const int*)d_in[11];
    const int* mol_ids = (const int*)d_in[12];

    float *p_inp, *p_msg0, *p_msg1, *p_amsg, *p_molsum, *p_wsum;
    ushort *p_wih, *p_wil, *p_whh, *p_whl, *p_woh, *p_wol;
    cudaGetSymbolAddress((void**)&p_inp, g_inp);
    cudaGetSymbolAddress((void**)&p_msg0, g_msg0);
    cudaGetSymbolAddress((void**)&p_msg1, g_msg1);
    cudaGetSymbolAddress((void**)&p_amsg, g_amsg);
    cudaGetSymbolAddress((void**)&p_molsum, g_molsum);
    cudaGetSymbolAddress((void**)&p_wsum, g_wsum);
    cudaGetSymbolAddress((void**)&p_wih, g_wi_hi);
    cudaGetSymbolAddress((void**)&p_wil, g_wi_lo);
    cudaGetSymbolAddress((void**)&p_whh, g_wh_hi);
    cudaGetSymbolAddress((void**)&p_whl, g_wh_lo);
    cudaGetSymbolAddress((void**)&p_woh, g_wo_hi);
    cudaGetSymbolAddress((void**)&p_wol, g_wo_lo);

    cudaFuncSetAttribute(hgemm<0>, cudaFuncAttributeMaxDynamicSharedMemorySize, SMEM_TOTAL);
    cudaFuncSetAttribute(hgemm<1>, cudaFuncAttributeMaxDynamicSharedMemorySize, SMEM_TOTAL);
    cudaFuncSetAttribute(hgemm<2>, cudaFuncAttributeMaxDynamicSharedMemorySize, SMEM_TOTAL);

    // launch order arranged so ncu (-s 5 -c 1) captures hgemm<0>:
    // 1 zero, 2 wsum, 3-5 prepack, 6 hgemm<0>
    zero_kernel<<<NM, 256>>>(p_molsum, p_wsum);
    wsum_kernel<<<(NA + 255) / 256, 256>>>(w_atoms, mol_ids, p_wsum);
    prepack_w<<<(256 * KP0 + 255) / 256, 256>>>(W_i, p_wih, p_wil, BF, KP0);
    prepack_w<<<(256 * KP1 + 255) / 256, 256>>>(W_h, p_whh, p_whl, H, KP1);
    prepack_w<<<(256 * KP2 + 255) / 256, 256>>>(W_o, p_woh, p_wol, AF + H, KP2);

    dim3 gb(MT_B, 2), ga(MT_A, 2);

    // input layer: inp = f_bonds @ W_i  (relu applied by readers)
    TArgs g0 = {};
    g0.A = f_bonds; g0.w_hi = p_wih; g0.w_lo = p_wil;
    g0.inp_out = p_inp; g0.M = NB;
    hgemm<0><<<gb, 256, SMEM_TOTAL>>>(g0);

    // depth iter 1 (sources: relu(inp) via relu-on-read)
    gather_kernel<<<NA / 4, 256>>>(p_inp, w_bonds, a2b, p_amsg);
    TArgs g1 = {};
    g1.w_hi = p_whh; g1.w_lo = p_whl; g1.amsg = p_amsg; g1.msgc = p_inp;
    g1.b2a = b2a; g1.b2revb = b2revb; g1.inp = p_inp; g1.msg_out = p_msg1; g1.M = NB;
    hgemm<1><<<gb, 256, SMEM_TOTAL>>>(g1);

    // depth iter 2
    gather_kernel<<<NA / 4, 256>>>(p_msg1, w_bonds, a2b, p_amsg);
    TArgs g2 = g1;
    g2.msgc = p_msg1; g2.msg_out = p_msg0;
    hgemm<1><<<gb, 256, SMEM_TOTAL>>>(g2);

    // readout
    gather_kernel<<<NA / 4, 256>>>(p_msg0, w_bonds, a2b, p_amsg);

    // atom readout GEMM -> hidden*w rows into g_msg1 scratch
    TArgs g3 = {};
    g3.fatoms = f_atoms; g3.amsg = p_amsg; g3.w_hi = p_woh; g3.w_lo = p_wol;
    g3.b_o = b_o; g3.w_atoms = w_atoms; g3.msg_out = p_msg1; g3.M = NA;
    hgemm<2><<<ga, 256, SMEM_TOTAL>>>(g3);

    segreduce_kernel<<<dim3(MT_A, 2), 256>>>(p_msg1, mol_ids, p_molsum);
    finalize_kernel<<<NM, 256>>>(p_molsum, p_wsum, deg, (float*)d_out);
}

// round 14
// speedup vs baseline: 1.2692x; 1.2692x over previous
#include <cuda_runtime.h>
#include <cuda_bf16.h>
#include <cstdint>

#define H 256
#define NA 100000
#define NB 250000
#define NM 2000
#define AF 133
#define BF 147
#define MAXNB 6

#define MT_B 1954          // ceil(250000/128)
#define MT_A 782           // ceil(100000/128)
#define KP0 192
#define KP1 256
#define KP2 448

typedef long long ll;
typedef unsigned int uint;
typedef unsigned short ushort;
typedef unsigned long long ull;

// ---------------- device scratch (allocation-guard-safe) ----------------
__device__ float  g_inp[(ll)NB * H];
__device__ float  g_msg0[(ll)NB * H];   // iter2 output
__device__ float  g_msg1[(ll)NB * H];   // iter1 output / atom_hidden scratch
__device__ float  g_amsg[(ll)NA * H];
__device__ ushort g_wi_hi[256 * KP0], g_wi_lo[256 * KP0];
__device__ ushort g_wh_hi[256 * KP1], g_wh_lo[256 * KP1];
__device__ ushort g_wo_hi[256 * KP2], g_wo_lo[256 * KP2];
__device__ float  g_molsum[NM * H];
__device__ float  g_wsum[NM];

// ---------------- helpers ----------------
__device__ __forceinline__ uint smem_u32(const void* p) {
    uint a;
    asm("{ .reg .u64 t; cvta.to.shared.u64 t, %1; cvt.u32.u64 %0, t; }" : "=r"(a) : "l"(p));
    return a;
}
__device__ __forceinline__ uint hi_pair(float a, float b) {   // truncate-split hi
    uint r;
    asm("prmt.b32 %0, %1, %2, 0x7632;" : "=r"(r)
        : "r"(__float_as_uint(a)), "r"(__float_as_uint(b)));
    return r;
}
__device__ __forceinline__ uint lo_pair(float a, float b) {
    float la = a - __uint_as_float(__float_as_uint(a) & 0xFFFF0000u);
    float lb = b - __uint_as_float(__float_as_uint(b) & 0xFFFF0000u);
    __nv_bfloat162 t = __floats2bfloat162_rn(la, lb);
    return *(uint*)&t;
}
__device__ __forceinline__ void ldsm4(uint* r, uint addr) {
    asm volatile("ldmatrix.sync.aligned.m8n8.x4.shared.b16 {%0,%1,%2,%3}, [%4];"
                 : "=r"(r[0]), "=r"(r[1]), "=r"(r[2]), "=r"(r[3]) : "r"(addr));
}
__device__ __forceinline__ void mma16816(float* d, const uint* a, const uint* b) {
    asm volatile(
        "mma.sync.aligned.m16n8k16.row.col.f32.bf16.bf16.f32 "
        "{%0,%1,%2,%3}, {%4,%5,%6,%7}, {%8,%9}, {%0,%1,%2,%3};"
        : "+f"(d[0]), "+f"(d[1]), "+f"(d[2]), "+f"(d[3])
        : "r"(a[0]), "r"(a[1]), "r"(a[2]), "r"(a[3]), "r"(b[0]), "r"(b[1]));
}
__device__ __forceinline__ void cp16(uint dst, const void* src) {
    asm volatile("cp.async.ca.shared.global [%0], [%1], 16;" :: "r"(dst), "l"(src));
}
__device__ __forceinline__ void cp_commit() {
    asm volatile("cp.async.commit_group;" ::: "memory");
}
__device__ __forceinline__ void cp_wait0() {
    asm volatile("cp.async.wait_group 0;" ::: "memory");
}

// SMEM: 2 buffers x 4 planes x (128 rows x 40 bf16, 80B stride)
#define PLNB 10240
#define BUFB (4 * PLNB)          // 40960
#define SMEM_TOTAL (2 * BUFB)    // 81920

struct TArgs {
    const float* A;                      // mode0: f_bonds
    const ushort *w_hi, *w_lo;           // pre-split weights [256 x KPAD], k-contig
    const float *amsg, *msgc;            // mode1 gather sources / mode2 amsg
    const int *b2a, *b2revb;
    const float* inp;                    // mode1 epilogue add
    const float* fatoms;                 // mode2
    float *inp_out, *msg_out;            // outputs (mode2: msg_out = hidden scratch)
    const float *b_o, *w_atoms;          // mode2
    int M;
};

template <int MODE>
__global__ __launch_bounds__(256, 1) void hgemm(TArgs g) {
    constexpr int KPAD = (MODE == 0) ? KP0 : ((MODE == 1) ? KP1 : KP2);
    constexpr int KT   = KPAD / 32;
    constexpr int KSRC = (MODE == 0) ? BF : ((MODE == 1) ? H : (AF + H));

    extern __shared__ char smem[];
    const uint sb = smem_u32(smem);

    const int tid = threadIdx.x;
    const int lane = tid & 31, wid = tid >> 5;
    const int wr = wid >> 1, wc = wid & 1;
    // L2-pairing: the two column-CTAs for the same row block are adjacent in
    // launch order (x is the 2-wide column dim), so the second one's random
    // A-row gathers hit L2 instead of DRAM.
    const int bm = blockIdx.y * 128;
    const int bn = blockIdx.x * 128;

    // loader geometry: thread -> (row2, k-half)
    const int row2 = tid >> 1, half = tid & 1;
    const int growl = bm + row2;
    const bool rv = growl < g.M;
    const float *p1 = nullptr, *p2 = nullptr;
    if (MODE == 1 && rv) {
        p1 = g.amsg + (ll)g.b2a[growl] * H;
        p2 = g.msgc + (ll)g.b2revb[growl] * H;
    }
    const ushort* wg_hi = g.w_hi + (ll)(bn + row2) * KPAD;
    const ushort* wg_lo = g.w_lo + (ll)(bn + row2) * KPAD;

    // ldmatrix lane addresses (buffer-relative)
    const int a_row = (lane & 7) + ((lane >> 3) & 1) * 8;
    const int a_k   = (lane >> 4) * 8;
    const uint offA = ((uint)((wr * 32 + a_row) * 40 + a_k) << 1);
    const int b_n = (lane & 7) + (lane >> 4) * 8;
    const int b_k = ((lane >> 3) & 1) * 8;
    const uint offB = 2 * PLNB + ((uint)((wc * 64 + b_n) * 40 + b_k) << 1);

    float acc[2][8][4];
#pragma unroll
    for (int mi = 0; mi < 2; mi++)
#pragma unroll
        for (int ni = 0; ni < 8; ni++)
#pragma unroll
            for (int q = 0; q < 4; q++) acc[mi][ni][q] = 0.f;

    float pv[16];

    auto prefetchA = [&](int c) {
        const int kbase = c * 32 + half * 16;
        if (MODE == 1) {
#pragma unroll
            for (int i = 0; i < 4; i++) {
                float4 x = rv ? *(const float4*)(p1 + kbase + i * 4) : make_float4(0, 0, 0, 0);
                float4 y = rv ? *(const float4*)(p2 + kbase + i * 4) : make_float4(0, 0, 0, 0);
                // relu-on-read of reverse message (idempotent on iter-2 input)
                pv[4 * i + 0] = x.x - fmaxf(y.x, 0.f);
                pv[4 * i + 1] = x.y - fmaxf(y.y, 0.f);
                pv[4 * i + 2] = x.z - fmaxf(y.z, 0.f);
                pv[4 * i + 3] = x.w - fmaxf(y.w, 0.f);
            }
        } else {
#pragma unroll
            for (int t = 0; t < 16; t++) {
                int k = kbase + t;
                float v = 0.f;
                if (rv && k < KSRC) {
                    if (MODE == 0) v = __ldg(&g.A[(ll)growl * BF + k]);
                    else v = (k < AF) ? __ldg(&g.fatoms[(ll)growl * AF + k])
                                      : __ldg(&g.amsg[(ll)growl * H + (k - AF)]);
                }
                pv[t] = v;
            }
        }
    };
    auto cpB = [&](int c, int s) {
        const int kbase = c * 32 + half * 16;
        const uint dst = sb + (uint)s * BUFB + (uint)(row2 * 80 + half * 32);
        cp16(dst + 2 * PLNB,      wg_hi + kbase);
        cp16(dst + 2 * PLNB + 16, wg_hi + kbase + 8);
        cp16(dst + 3 * PLNB,      wg_lo + kbase);
        cp16(dst + 3 * PLNB + 16, wg_lo + kbase + 8);
    };
    auto stsA = [&](int s) {
        char* base = smem + (size_t)s * BUFB;
        uint ao = (uint)(row2 * 40 + half * 16);
#pragma unroll
        for (int i = 0; i < 4; i++) {
            uint2 hv = make_uint2(hi_pair(pv[4 * i], pv[4 * i + 1]),
                                  hi_pair(pv[4 * i + 2], pv[4 * i + 3]));
            uint2 lv = make_uint2(lo_pair(pv[4 * i], pv[4 * i + 1]),
                                  lo_pair(pv[4 * i + 2], pv[4 * i + 3]));
            *(uint2*)(base + ((ao + i * 4) << 1)) = hv;
            *(uint2*)(base + PLNB + ((ao + i * 4) << 1)) = lv;
        }
    };

    // prologue: fill buffer 0
    prefetchA(0);
    cpB(0, 0);
    cp_commit();
    stsA(0);
    cp_wait0();
    __syncthreads();

    for (int c = 0; c < KT; c++) {
        const int s = c & 1, ns = s ^ 1;
        if (c + 1 < KT) { prefetchA(c + 1); cpB(c + 1, ns); }
        cp_commit();

        // ---- compute chunk c from buffer s ----
        const uint bufo = sb + (uint)s * BUFB;
#pragma unroll
        for (int ks = 0; ks < 2; ks++) {
            const uint kb2 = (uint)(ks * 32);
            uint Ah[2][4], Al[2][4], Bh[4][4], Bl[4][4];
#pragma unroll
            for (int mi = 0; mi < 2; mi++) {
                ldsm4(Ah[mi], bufo + offA + kb2 + mi * 1280);
                ldsm4(Al[mi], bufo + offA + PLNB + kb2 + mi * 1280);
            }
#pragma unroll
            for (int nt = 0; nt < 4; nt++) {
                ldsm4(Bh[nt], bufo + offB + kb2 + nt * 1280);
                ldsm4(Bl[nt], bufo + offB + PLNB + kb2 + nt * 1280);
            }
#pragma unroll
            for (int mi = 0; mi < 2; mi++)
#pragma unroll
                for (int nt = 0; nt < 4; nt++)
#pragma unroll
                    for (int sub = 0; sub < 2; sub++) {
                        const int ni = nt * 2 + sub;
                        mma16816(acc[mi][ni], Ah[mi], &Bh[nt][sub * 2]);
                        mma16816(acc[mi][ni], Ah[mi], &Bl[nt][sub * 2]);
                        mma16816(acc[mi][ni], Al[mi], &Bh[nt][sub * 2]);
                    }
        }

        if (c + 1 < KT) stsA(ns);
        cp_wait0();
        __syncthreads();
    }

    // ---------------- epilogue ----------------
    const int grp = lane >> 2, qi = lane & 3;
#pragma unroll
    for (int mi = 0; mi < 2; mi++) {
        const int r0 = bm + wr * 32 + mi * 16 + grp;
        const int r1 = r0 + 8;
        float w0 = 0.f, w1 = 0.f;
        if (MODE == 2) {
            w0 = (r0 < g.M) ? __ldg(&g.w_atoms[r0]) : 0.f;
            w1 = (r1 < g.M) ? __ldg(&g.w_atoms[r1]) : 0.f;
        }
#pragma unroll
        for (int ni = 0; ni < 8; ni++) {
            const int col = bn + wc * 64 + ni * 8 + qi * 2;
            float c0 = acc[mi][ni][0], c1 = acc[mi][ni][1];
            float c2 = acc[mi][ni][2], c3 = acc[mi][ni][3];
            if (MODE == 0) {
                if (r0 < g.M) *(float2*)&g.inp_out[(ll)r0 * H + col] = make_float2(c0, c1);
                if (r1 < g.M) *(float2*)&g.inp_out[(ll)r1 * H + col] = make_float2(c2, c3);
            } else if (MODE == 1) {
                if (r0 < g.M) {
                    float2 iv = *(const float2*)&g.inp[(ll)r0 * H + col];
                    *(float2*)&g.msg_out[(ll)r0 * H + col] =
                        make_float2(fmaxf(c0 + iv.x, 0.f), fmaxf(c1 + iv.y, 0.f));
                }
                if (r1 < g.M) {
                    float2 iv = *(const float2*)&g.inp[(ll)r1 * H + col];
                    *(float2*)&g.msg_out[(ll)r1 * H + col] =
                        make_float2(fmaxf(c2 + iv.x, 0.f), fmaxf(c3 + iv.y, 0.f));
                }
            } else {
                float2 bo = *(const float2*)&g.b_o[col];
                if (r0 < g.M)
                    *(float2*)&g.msg_out[(ll)r0 * H + col] =
                        make_float2(fmaxf(c0 + bo.x, 0.f) * w0, fmaxf(c1 + bo.y, 0.f) * w0);
                if (r1 < g.M)
                    *(float2*)&g.msg_out[(ll)r1 * H + col] =
                        make_float2(fmaxf(c2 + bo.x, 0.f) * w1, fmaxf(c3 + bo.y, 0.f) * w1);
            }
        }
    }
}

// ---------------- weight prepack: [K x 256] fp32 -> [256 x Kpad] bf16 hi/lo ----
__global__ void prepack_w(const float* __restrict__ src, ushort* __restrict__ hi,
                          ushort* __restrict__ lo, int K, int Kpad) {
    int idx = blockIdx.x * 256 + threadIdx.x;
    if (idx >= 256 * Kpad) return;
    int n = idx / Kpad, k = idx - n * Kpad;
    float v = (k < K) ? src[(ll)k * 256 + n] : 0.f;
    uint u = __float_as_uint(v);
    hi[idx] = (ushort)(u >> 16);
    float lv = v - __uint_as_float(u & 0xFFFF0000u);
    __nv_bfloat16 b = __float2bfloat16(lv);
    lo[idx] = *(ushort*)&b;
}

// ---------------- small kernels ----------------
// relu applied on read (idempotent for already-relu'd buffers)
__global__ __launch_bounds__(256) void gather_kernel(const float* __restrict__ msg,
                                                     const float* __restrict__ w_bonds,
                                                     const int* __restrict__ a2b,
                                                     float* __restrict__ amsg) {
    int tid = threadIdx.x;
    int a = blockIdx.x * 4 + (tid >> 6);
    int lane = tid & 63;
    float4 s = make_float4(0.f, 0.f, 0.f, 0.f);
#pragma unroll
    for (int j = 0; j < MAXNB; j++) {
        int b = a2b[a * MAXNB + j];
        float w = w_bonds[b];
        float4 mv = *(const float4*)&msg[(ll)b * H + lane * 4];
        s.x += w * fmaxf(mv.x, 0.f); s.y += w * fmaxf(mv.y, 0.f);
        s.z += w * fmaxf(mv.z, 0.f); s.w += w * fmaxf(mv.w, 0.f);
    }
    *(float4*)&amsg[(ll)a * H + lane * 4] = s;
}

__global__ void zero_kernel(float* molsum, float* wsum) {
    int i = blockIdx.x * 256 + threadIdx.x;
    if (i < NM * H) molsum[i] = 0.f;
    if (i < NM) wsum[i] = 0.f;
}
__global__ void wsum_kernel(const float* __restrict__ w_atoms, const int* __restrict__ mol_ids,
                            float* __restrict__ wsum) {
    int i = blockIdx.x * 256 + threadIdx.x;
    if (i < NA) atomicAdd(&wsum[mol_ids[i]], w_atoms[i]);
}

__global__ __launch_bounds__(256) void segreduce_kernel(const float* __restrict__ hid,
                                                        const int* __restrict__ mol_ids,
                                                        float* __restrict__ molsum) {
    int col = blockIdx.y * 128 + (threadIdx.x & 127);
    int rbase = blockIdx.x * 128 + (threadIdx.x >> 7) * 64;
    if (rbase >= NA) return;
    int rend = rbase + 64; if (rend > NA) rend = NA;
    int cur = -1; float s = 0.f;
    for (int r = rbase; r < rend; r++) {
        int m = __ldg(&mol_ids[r]);
        float v = hid[(ll)r * H + col];
        if (m != cur) {
            if (cur >= 0) atomicAdd(&molsum[(ll)cur * H + col], s);
            cur = m; s = 0.f;
        }
        s += v;
    }
    if (cur >= 0) atomicAdd(&molsum[(ll)cur * H + col], s);
}

__global__ void finalize_kernel(const float* __restrict__ molsum, const float* __restrict__ wsum,
                                const float* __restrict__ deg, float* __restrict__ out) {
    int m = blockIdx.x, hc = threadIdx.x;
    float w = wsum[m];
    float v = (w > 0.f) ? molsum[m * H + hc] / w : 0.f;
    out[m * H + hc] = deg[m] * v;
}

extern "C" void kernel_launch(void* const* d_in, const int* in_sizes, int n_in,
                              void* d_out, int out_size) {
    const float* f_atoms = (const float*)d_in[0];
    const float* f_bonds = (const float*)d_in[1];
    const float* w_atoms = (const float*)d_in[2];
    const float* w_bonds = (const float*)d_in[3];
    const float* W_i = (const float*)d_in[4];
    const float* W_h = (const float*)d_in[5];
    const float* W_o = (const float*)d_in[6];
    const float* b_o = (const float*)d_in[7];
    const float* deg = (const float*)d_in[8];
    const int* a2b = (const int*)d_in[9];
    const int* b2a = (const int*)d_in[10];
    const int* b2revb = (const int*)d_in[11];
    const int* mol_ids = (const int*)d_in[12];

    float *p_inp, *p_msg0, *p_msg1, *p_amsg, *p_molsum, *p_wsum;
    ushort *p_wih, *p_wil, *p_whh, *p_whl, *p_woh, *p_wol;
    cudaGetSymbolAddress((void**)&p_inp, g_inp);
    cudaGetSymbolAddress((void**)&p_msg0, g_msg0);
    cudaGetSymbolAddress((void**)&p_msg1, g_msg1);
    cudaGetSymbolAddress((void**)&p_amsg, g_amsg);
    cudaGetSymbolAddress((void**)&p_molsum, g_molsum);
    cudaGetSymbolAddress((void**)&p_wsum, g_wsum);
    cudaGetSymbolAddress((void**)&p_wih, g_wi_hi);
    cudaGetSymbolAddress((void**)&p_wil, g_wi_lo);
    cudaGetSymbolAddress((void**)&p_whh, g_wh_hi);
    cudaGetSymbolAddress((void**)&p_whl, g_wh_lo);
    cudaGetSymbolAddress((void**)&p_woh, g_wo_hi);
    cudaGetSymbolAddress((void**)&p_wol, g_wo_lo);

    cudaFuncSetAttribute(hgemm<0>, cudaFuncAttributeMaxDynamicSharedMemorySize, SMEM_TOTAL);
    cudaFuncSetAttribute(hgemm<1>, cudaFuncAttributeMaxDynamicSharedMemorySize, SMEM_TOTAL);
    cudaFuncSetAttribute(hgemm<2>, cudaFuncAttributeMaxDynamicSharedMemorySize, SMEM_TOTAL);

    zero_kernel<<<NM, 256>>>(p_molsum, p_wsum);
    wsum_kernel<<<(NA + 255) / 256, 256>>>(w_atoms, mol_ids, p_wsum);
    prepack_w<<<(256 * KP0 + 255) / 256, 256>>>(W_i, p_wih, p_wil, BF, KP0);
    prepack_w<<<(256 * KP1 + 255) / 256, 256>>>(W_h, p_whh, p_whl, H, KP1);
    prepack_w<<<(256 * KP2 + 255) / 256, 256>>>(W_o, p_woh, p_wol, AF + H, KP2);

    // grids: x = 2 column blocks (adjacent -> L2 pairing), y = row blocks
    dim3 gb(2, MT_B), ga(2, MT_A);

    // input layer: inp = f_bonds @ W_i  (relu applied by readers)
    TArgs g0 = {};
    g0.A = f_bonds; g0.w_hi = p_wih; g0.w_lo = p_wil;
    g0.inp_out = p_inp; g0.M = NB;
    hgemm<0><<<gb, 256, SMEM_TOTAL>>>(g0);

    // depth iter 1 (sources: relu(inp) via relu-on-read)
    gather_kernel<<<NA / 4, 256>>>(p_inp, w_bonds, a2b, p_amsg);
    TArgs g1 = {};
    g1.w_hi = p_whh; g1.w_lo = p_whl; g1.amsg = p_amsg; g1.msgc = p_inp;
    g1.b2a = b2a; g1.b2revb = b2revb; g1.inp = p_inp; g1.msg_out = p_msg1; g1.M = NB;
    hgemm<1><<<gb, 256, SMEM_TOTAL>>>(g1);

    // depth iter 2
    gather_kernel<<<NA / 4, 256>>>(p_msg1, w_bonds, a2b, p_amsg);
    TArgs g2 = g1;
    g2.msgc = p_msg1; g2.msg_out = p_msg0;
    hgemm<1><<<gb, 256, SMEM_TOTAL>>>(g2);

    // readout
    gather_kernel<<<NA / 4, 256>>>(p_msg0, w_bonds, a2b, p_amsg);

    // atom readout GEMM -> hidden*w rows into g_msg1 scratch
    TArgs g3 = {};
    g3.fatoms = f_atoms; g3.amsg = p_amsg; g3.w_hi = p_woh; g3.w_lo = p_wol;
    g3.b_o = b_o; g3.w_atoms = w_atoms; g3.msg_out = p_msg1; g3.M = NA;
    hgemm<2><<<ga, 256, SMEM_TOTAL>>>(g3);

    segreduce_kernel<<<dim3(MT_A, 2), 256>>>(p_msg1, mol_ids, p_molsum);
    finalize_kernel<<<NM, 256>>>(p_molsum, p_wsum, deg, (float*)d_out);
}

// round 15
// speedup vs baseline: 1.8671x; 1.4711x over previous
#include <cuda_runtime.h>
#include <cuda_bf16.h>
#include <cstdint>

#define H 256
#define NA 100000
#define NB 250000
#define NM 2000
#define AF 133
#define BF 147
#define MAXNB 6

#define MT_B 1954          // ceil(250000/128)
#define MT_A 782           // ceil(100000/128)
#define KP0 192
#define KP1 256
#define KP2 448

typedef long long ll;
typedef unsigned int uint;
typedef unsigned short ushort;
typedef unsigned long long ull;

// ---------------- device scratch (allocation-guard-safe) ----------------
__device__ float  g_inp[(ll)NB * H];
__device__ float  g_msg0[(ll)NB * H];   // iter2 output
__device__ float  g_msg1[(ll)NB * H];   // iter1 output / atom_hidden scratch
__device__ float  g_amsg[(ll)NA * H];
__device__ ushort g_wi_hi[256 * KP0], g_wi_lo[256 * KP0];
__device__ ushort g_wh_hi[256 * KP1], g_wh_lo[256 * KP1];
__device__ ushort g_wo_hi[256 * KP2], g_wo_lo[256 * KP2];
__device__ float  g_molsum[NM * H];
__device__ float  g_wsum[NM];

// ---------------- helpers ----------------
__device__ __forceinline__ uint smem_u32(const void* p) {
    uint a;
    asm("{ .reg .u64 t; cvta.to.shared.u64 t, %1; cvt.u32.u64 %0, t; }" : "=r"(a) : "l"(p));
    return a;
}
__device__ __forceinline__ uint hi_pair(float a, float b) {   // truncate-split hi
    uint r;
    asm("prmt.b32 %0, %1, %2, 0x7632;" : "=r"(r)
        : "r"(__float_as_uint(a)), "r"(__float_as_uint(b)));
    return r;
}
__device__ __forceinline__ uint lo_pair(float a, float b) {
    float la = a - __uint_as_float(__float_as_uint(a) & 0xFFFF0000u);
    float lb = b - __uint_as_float(__float_as_uint(b) & 0xFFFF0000u);
    __nv_bfloat162 t = __floats2bfloat162_rn(la, lb);
    return *(uint*)&t;
}
__device__ __forceinline__ void ldsm4(uint* r, uint addr) {
    asm volatile("ldmatrix.sync.aligned.m8n8.x4.shared.b16 {%0,%1,%2,%3}, [%4];"
                 : "=r"(r[0]), "=r"(r[1]), "=r"(r[2]), "=r"(r[3]) : "r"(addr));
}
__device__ __forceinline__ void mma16816(float* d, const uint* a, const uint* b) {
    asm volatile(
        "mma.sync.aligned.m16n8k16.row.col.f32.bf16.bf16.f32 "
        "{%0,%1,%2,%3}, {%4,%5,%6,%7}, {%8,%9}, {%0,%1,%2,%3};"
        : "+f"(d[0]), "+f"(d[1]), "+f"(d[2]), "+f"(d[3])
        : "r"(a[0]), "r"(a[1]), "r"(a[2]), "r"(a[3]), "r"(b[0]), "r"(b[1]));
}
__device__ __forceinline__ void cp16(uint dst, const void* src) {
    asm volatile("cp.async.ca.shared.global [%0], [%1], 16;" :: "r"(dst), "l"(src));
}
__device__ __forceinline__ void cp_commit() {
    asm volatile("cp.async.commit_group;" ::: "memory");
}
__device__ __forceinline__ void cp_wait0() {
    asm volatile("cp.async.wait_group 0;" ::: "memory");
}

// SMEM per stage: Ah 10240 | Al 10240 | Bh 20480 | Bl 20480  (rows: 40 bf16, 80B stride)
#define APLN 10240
#define BPLN 20480
#define OFF_AL 10240
#define OFF_BH 20480
#define OFF_BL 40960
#define BUFB 61440
#define SMEM_TOTAL (2 * BUFB)    // 122880

struct TArgs {
    const float* A;                      // mode0: f_bonds
    const ushort *w_hi, *w_lo;           // pre-split weights [256 x KPAD], k-contig
    const float *amsg, *msgc;            // mode1 gather sources / mode2 amsg
    const int *b2a, *b2revb;
    const float* inp;                    // mode1 epilogue add
    const float* fatoms;                 // mode2
    float *inp_out, *msg_out;            // outputs (mode2: msg_out = hidden scratch)
    const float *b_o, *w_atoms;          // mode2
    int M;
};

// 512 threads: 16 warps in 4(row) x 4(col); CTA tile 128 x 256.
template <int MODE>
__global__ __launch_bounds__(512, 1) void hgemm(TArgs g) {
    constexpr int KPAD = (MODE == 0) ? KP0 : ((MODE == 1) ? KP1 : KP2);
    constexpr int KT   = KPAD / 32;
    constexpr int KSRC = (MODE == 0) ? BF : ((MODE == 1) ? H : (AF + H));

    extern __shared__ char smem[];
    const uint sb = smem_u32(smem);

    const int tid = threadIdx.x;
    const int lane = tid & 31, wid = tid >> 5;
    const int wr = wid >> 2, wc = wid & 3;
    const int bm = blockIdx.x * 128;

    // ---- A loader geometry: 4 threads per row, 8 k each ----
    const int rowA = tid >> 2, qA = tid & 3;
    const int growl = bm + rowA;
    const bool rv = growl < g.M;
    const float *p1 = nullptr, *p2 = nullptr;
    if (MODE == 1 && rv) {
        p1 = g.amsg + (ll)g.b2a[growl] * H;
        p2 = g.msgc + (ll)g.b2revb[growl] * H;
    }
    // ---- B loader geometry: 2 threads per row (256 rows), 16 k each ----
    const int rowB = tid >> 1, halfB = tid & 1;
    const ushort* wg_hi = g.w_hi + (ll)rowB * KPAD;
    const ushort* wg_lo = g.w_lo + (ll)rowB * KPAD;

    // ldmatrix lane addresses (buffer-relative)
    const int a_row = (lane & 7) + ((lane >> 3) & 1) * 8;
    const int a_k   = (lane >> 4) * 8;
    const uint offA = ((uint)((wr * 32 + a_row) * 40 + a_k) << 1);
    const int b_n = (lane & 7) + (lane >> 4) * 8;
    const int b_k = ((lane >> 3) & 1) * 8;
    const uint offB = OFF_BH + ((uint)((wc * 64 + b_n) * 40 + b_k) << 1);

    float acc[2][8][4];
#pragma unroll
    for (int mi = 0; mi < 2; mi++)
#pragma unroll
        for (int ni = 0; ni < 8; ni++)
#pragma unroll
            for (int q = 0; q < 4; q++) acc[mi][ni][q] = 0.f;

    float pv[8];

    auto prefetchA = [&](int c) {
        const int kbase = c * 32 + qA * 8;
        if (MODE == 1) {
            float4 x0 = rv ? *(const float4*)(p1 + kbase)     : make_float4(0, 0, 0, 0);
            float4 x1 = rv ? *(const float4*)(p1 + kbase + 4) : make_float4(0, 0, 0, 0);
            float4 y0 = rv ? *(const float4*)(p2 + kbase)     : make_float4(0, 0, 0, 0);
            float4 y1 = rv ? *(const float4*)(p2 + kbase + 4) : make_float4(0, 0, 0, 0);
            pv[0] = x0.x - fmaxf(y0.x, 0.f); pv[1] = x0.y - fmaxf(y0.y, 0.f);
            pv[2] = x0.z - fmaxf(y0.z, 0.f); pv[3] = x0.w - fmaxf(y0.w, 0.f);
            pv[4] = x1.x - fmaxf(y1.x, 0.f); pv[5] = x1.y - fmaxf(y1.y, 0.f);
            pv[6] = x1.z - fmaxf(y1.z, 0.f); pv[7] = x1.w - fmaxf(y1.w, 0.f);
        } else {
#pragma unroll
            for (int t = 0; t < 8; t++) {
                int k = kbase + t;
                float v = 0.f;
                if (rv && k < KSRC) {
                    if (MODE == 0) v = __ldg(&g.A[(ll)growl * BF + k]);
                    else v = (k < AF) ? __ldg(&g.fatoms[(ll)growl * AF + k])
                                      : __ldg(&g.amsg[(ll)growl * H + (k - AF)]);
                }
                pv[t] = v;
            }
        }
    };
    auto cpB = [&](int c, int s) {
        const int kbase = c * 32 + halfB * 16;
        const uint dst = sb + (uint)s * BUFB + (uint)(rowB * 80 + halfB * 32);
        cp16(dst + OFF_BH,      wg_hi + kbase);
        cp16(dst + OFF_BH + 16, wg_hi + kbase + 8);
        cp16(dst + OFF_BL,      wg_lo + kbase);
        cp16(dst + OFF_BL + 16, wg_lo + kbase + 8);
    };
    auto stsA = [&](int s) {
        char* base = smem + (size_t)s * BUFB;
        uint ao = (uint)(rowA * 40 + qA * 8);
        uint4 hv = make_uint4(hi_pair(pv[0], pv[1]), hi_pair(pv[2], pv[3]),
                              hi_pair(pv[4], pv[5]), hi_pair(pv[6], pv[7]));
        uint4 lv = make_uint4(lo_pair(pv[0], pv[1]), lo_pair(pv[2], pv[3]),
                              lo_pair(pv[4], pv[5]), lo_pair(pv[6], pv[7]));
        *(uint4*)(base + (ao << 1))          = hv;
        *(uint4*)(base + OFF_AL + (ao << 1)) = lv;
    };

    // prologue: fill buffer 0
    prefetchA(0);
    cpB(0, 0);
    cp_commit();
    stsA(0);
    cp_wait0();
    __syncthreads();

    for (int c = 0; c < KT; c++) {
        const int s = c & 1, ns = s ^ 1;
        if (c + 1 < KT) { prefetchA(c + 1); cpB(c + 1, ns); }
        cp_commit();

        // ---- compute chunk c from buffer s ----
        const uint bufo = sb + (uint)s * BUFB;
#pragma unroll
        for (int ks = 0; ks < 2; ks++) {
            const uint kb2 = (uint)(ks * 32);
            uint Ah[2][4], Al[2][4], Bh[4][4], Bl[4][4];
#pragma unroll
            for (int mi = 0; mi < 2; mi++) {
                ldsm4(Ah[mi], bufo + offA + kb2 + mi * 1280);
                ldsm4(Al[mi], bufo + offA + OFF_AL + kb2 + mi * 1280);
            }
#pragma unroll
            for (int nt = 0; nt < 4; nt++) {
                ldsm4(Bh[nt], bufo + offB + kb2 + nt * 1280);
                ldsm4(Bl[nt], bufo + offB + BPLN + kb2 + nt * 1280);
            }
#pragma unroll
            for (int mi = 0; mi < 2; mi++)
#pragma unroll
                for (int nt = 0; nt < 4; nt++)
#pragma unroll
                    for (int sub = 0; sub < 2; sub++) {
                        const int ni = nt * 2 + sub;
                        mma16816(acc[mi][ni], Ah[mi], &Bh[nt][sub * 2]);
                        mma16816(acc[mi][ni], Ah[mi], &Bl[nt][sub * 2]);
                        mma16816(acc[mi][ni], Al[mi], &Bh[nt][sub * 2]);
                    }
        }

        if (c + 1 < KT) stsA(ns);
        cp_wait0();
        __syncthreads();
    }

    // ---------------- epilogue ----------------
    const int grp = lane >> 2, qi = lane & 3;
#pragma unroll
    for (int mi = 0; mi < 2; mi++) {
        const int r0 = bm + wr * 32 + mi * 16 + grp;
        const int r1 = r0 + 8;
        float w0 = 0.f, w1 = 0.f;
        if (MODE == 2) {
            w0 = (r0 < g.M) ? __ldg(&g.w_atoms[r0]) : 0.f;
            w1 = (r1 < g.M) ? __ldg(&g.w_atoms[r1]) : 0.f;
        }
#pragma unroll
        for (int ni = 0; ni < 8; ni++) {
            const int col = wc * 64 + ni * 8 + qi * 2;
            float c0 = acc[mi][ni][0], c1 = acc[mi][ni][1];
            float c2 = acc[mi][ni][2], c3 = acc[mi][ni][3];
            if (MODE == 0) {
                if (r0 < g.M) *(float2*)&g.inp_out[(ll)r0 * H + col] = make_float2(c0, c1);
                if (r1 < g.M) *(float2*)&g.inp_out[(ll)r1 * H + col] = make_float2(c2, c3);
            } else if (MODE == 1) {
                if (r0 < g.M) {
                    float2 iv = *(const float2*)&g.inp[(ll)r0 * H + col];
                    *(float2*)&g.msg_out[(ll)r0 * H + col] =
                        make_float2(fmaxf(c0 + iv.x, 0.f), fmaxf(c1 + iv.y, 0.f));
                }
                if (r1 < g.M) {
                    float2 iv = *(const float2*)&g.inp[(ll)r1 * H + col];
                    *(float2*)&g.msg_out[(ll)r1 * H + col] =
                        make_float2(fmaxf(c2 + iv.x, 0.f), fmaxf(c3 + iv.y, 0.f));
                }
            } else {
                float2 bo = *(const float2*)&g.b_o[col];
                if (r0 < g.M)
                    *(float2*)&g.msg_out[(ll)r0 * H + col] =
                        make_float2(fmaxf(c0 + bo.x, 0.f) * w0, fmaxf(c1 + bo.y, 0.f) * w0);
                if (r1 < g.M)
                    *(float2*)&g.msg_out[(ll)r1 * H + col] =
                        make_float2(fmaxf(c2 + bo.x, 0.f) * w1, fmaxf(c3 + bo.y, 0.f) * w1);
            }
        }
    }
}

// ---------------- merged weight prepack (single launch) ----------------
// [K x 256] fp32 -> [256 x Kpad] bf16 hi/lo, for all three weight matrices.
struct PArgs {
    const float *s0, *s1, *s2;
    ushort *h0, *l0, *h1, *l1, *h2, *l2;
};
__global__ void prepack_all(PArgs p) {
    int idx = blockIdx.x * 256 + threadIdx.x;
    const float* src; ushort *hi, *lo; int K, Kpad;
    if (idx < 256 * KP0) {
        src = p.s0; hi = p.h0; lo = p.l0; K = BF; Kpad = KP0;
    } else if (idx < 256 * (KP0 + KP1)) {
        idx -= 256 * KP0;
        src = p.s1; hi = p.h1; lo = p.l1; K = H; Kpad = KP1;
    } else {
        idx -= 256 * (KP0 + KP1);
        if (idx >= 256 * KP2) return;
        src = p.s2; hi = p.h2; lo = p.l2; K = AF + H; Kpad = KP2;
    }
    int n = idx / Kpad, k = idx - n * Kpad;
    float v = (k < K) ? src[(ll)k * 256 + n] : 0.f;
    uint u = __float_as_uint(v);
    hi[idx + n * 0] = (ushort)(u >> 16);
    float lv = v - __uint_as_float(u & 0xFFFF0000u);
    __nv_bfloat16 b = __float2bfloat16(lv);
    lo[idx] = *(ushort*)&b;
}

// ---------------- small kernels ----------------
__global__ __launch_bounds__(256) void gather_kernel(const float* __restrict__ msg,
                                                     const float* __restrict__ w_bonds,
                                                     const int* __restrict__ a2b,
                                                     float* __restrict__ amsg) {
    int tid = threadIdx.x;
    int a = blockIdx.x * 4 + (tid >> 6);
    int lane = tid & 63;
    float4 s = make_float4(0.f, 0.f, 0.f, 0.f);
#pragma unroll
    for (int j = 0; j < MAXNB; j++) {
        int b = a2b[a * MAXNB + j];
        float w = w_bonds[b];
        float4 mv = *(const float4*)&msg[(ll)b * H + lane * 4];
        s.x += w * fmaxf(mv.x, 0.f); s.y += w * fmaxf(mv.y, 0.f);
        s.z += w * fmaxf(mv.z, 0.f); s.w += w * fmaxf(mv.w, 0.f);
    }
    *(float4*)&amsg[(ll)a * H + lane * 4] = s;
}

__global__ void zero_kernel(float* molsum, float* wsum) {
    int i = blockIdx.x * 256 + threadIdx.x;
    if (i < NM * H) molsum[i] = 0.f;
    if (i < NM) wsum[i] = 0.f;
}
__global__ void wsum_kernel(const float* __restrict__ w_atoms, const int* __restrict__ mol_ids,
                            float* __restrict__ wsum) {
    int i = blockIdx.x * 256 + threadIdx.x;
    if (i < NA) atomicAdd(&wsum[mol_ids[i]], w_atoms[i]);
}

__global__ __launch_bounds__(256) void segreduce_kernel(const float* __restrict__ hid,
                                                        const int* __restrict__ mol_ids,
                                                        float* __restrict__ molsum) {
    int col = blockIdx.y * 128 + (threadIdx.x & 127);
    int rbase = blockIdx.x * 128 + (threadIdx.x >> 7) * 64;
    if (rbase >= NA) return;
    int rend = rbase + 64; if (rend > NA) rend = NA;
    int cur = -1; float s = 0.f;
    for (int r = rbase; r < rend; r++) {
        int m = __ldg(&mol_ids[r]);
        float v = hid[(ll)r * H + col];
        if (m != cur) {
            if (cur >= 0) atomicAdd(&molsum[(ll)cur * H + col], s);
            cur = m; s = 0.f;
        }
        s += v;
    }
    if (cur >= 0) atomicAdd(&molsum[(ll)cur * H + col], s);
}

__global__ void finalize_kernel(const float* __restrict__ molsum, const float* __restrict__ wsum,
                                const float* __restrict__ deg, float* __restrict__ out) {
    int m = blockIdx.x, hc = threadIdx.x;
    float w = wsum[m];
    float v = (w > 0.f) ? molsum[m * H + hc] / w : 0.f;
    out[m * H + hc] = deg[m] * v;
}

extern "C" void kernel_launch(void* const* d_in, const int* in_sizes, int n_in,
                              void* d_out, int out_size) {
    const float* f_atoms = (const float*)d_in[0];
    const float* f_bonds = (const float*)d_in[1];
    const float* w_atoms = (const float*)d_in[2];
    const float* w_bonds = (const float*)d_in[3];
    const float* W_i = (const float*)d_in[4];
    const float* W_h = (const float*)d_in[5];
    const float* W_o = (const float*)d_in[6];
    const float* b_o = (const float*)d_in[7];
    const float* deg = (const float*)d_in[8];
    const int* a2b = (const int*)d_in[9];
    const int* b2a = (const int*)d_in[10];
    const int* b2revb = (const int*)d_in[11];
    const int* mol_ids = (const int*)d_in[12];

    float *p_inp, *p_msg0, *p_msg1, *p_amsg, *p_molsum, *p_wsum;
    ushort *p_wih, *p_wil, *p_whh, *p_whl, *p_woh, *p_wol;
    cudaGetSymbolAddress((void**)&p_inp, g_inp);
    cudaGetSymbolAddress((void**)&p_msg0, g_msg0);
    cudaGetSymbolAddress((void**)&p_msg1, g_msg1);
    cudaGetSymbolAddress((void**)&p_amsg, g_amsg);
    cudaGetSymbolAddress((void**)&p_molsum, g_molsum);
    cudaGetSymbolAddress((void**)&p_wsum, g_wsum);
    cudaGetSymbolAddress((void**)&p_wih, g_wi_hi);
    cudaGetSymbolAddress((void**)&p_wil, g_wi_lo);
    cudaGetSymbolAddress((void**)&p_whh, g_wh_hi);
    cudaGetSymbolAddress((void**)&p_whl, g_wh_lo);
    cudaGetSymbolAddress((void**)&p_woh, g_wo_hi);
    cudaGetSymbolAddress((void**)&p_wol, g_wo_lo);

    cudaFuncSetAttribute(hgemm<0>, cudaFuncAttributeMaxDynamicSharedMemorySize, SMEM_TOTAL);
    cudaFuncSetAttribute(hgemm<1>, cudaFuncAttributeMaxDynamicSharedMemorySize, SMEM_TOTAL);
    cudaFuncSetAttribute(hgemm<2>, cudaFuncAttributeMaxDynamicSharedMemorySize, SMEM_TOTAL);

    // launch order: 1 zero, 2 wsum, 3 prepack_all, 4 hgemm<0>  (ncu captures #4)
    zero_kernel<<<NM, 256>>>(p_molsum, p_wsum);
    wsum_kernel<<<(NA + 255) / 256, 256>>>(w_atoms, mol_ids, p_wsum);
    PArgs pa = {W_i, W_h, W_o, p_wih, p_wil, p_whh, p_whl, p_woh, p_wol};
    prepack_all<<<(256 * (KP0 + KP1 + KP2) + 255) / 256, 256>>>(pa);

    // input layer: inp = f_bonds @ W_i  (relu applied by readers)
    TArgs g0 = {};
    g0.A = f_bonds; g0.w_hi = p_wih; g0.w_lo = p_wil;
    g0.inp_out = p_inp; g0.M = NB;
    hgemm<0><<<MT_B, 512, SMEM_TOTAL>>>(g0);

    // depth iter 1 (sources: relu(inp) via relu-on-read)
    gather_kernel<<<NA / 4, 256>>>(p_inp, w_bonds, a2b, p_amsg);
    TArgs g1 = {};
    g1.w_hi = p_whh; g1.w_lo = p_whl; g1.amsg = p_amsg; g1.msgc = p_inp;
    g1.b2a = b2a; g1.b2revb = b2revb; g1.inp = p_inp; g1.msg_out = p_msg1; g1.M = NB;
    hgemm<1><<<MT_B, 512, SMEM_TOTAL>>>(g1);

    // depth iter 2
    gather_kernel<<<NA / 4, 256>>>(p_msg1, w_bonds, a2b, p_amsg);
    TArgs g2 = g1;
    g2.msgc = p_msg1; g2.msg_out = p_msg0;
    hgemm<1><<<MT_B, 512, SMEM_TOTAL>>>(g2);

    // readout
    gather_kernel<<<NA / 4, 256>>>(p_msg0, w_bonds, a2b, p_amsg);

    // atom readout GEMM -> hidden*w rows into g_msg1 scratch
    TArgs g3 = {};
    g3.fatoms = f_atoms; g3.amsg = p_amsg; g3.w_hi = p_woh; g3.w_lo = p_wol;
    g3.b_o = b_o; g3.w_atoms = w_atoms; g3.msg_out = p_msg1; g3.M = NA;
    hgemm<2><<<MT_A, 512, SMEM_TOTAL>>>(g3);

    segreduce_kernel<<<dim3(MT_A, 2), 256>>>(p_msg1, mol_ids, p_molsum);
    finalize_kernel<<<NM, 256>>>(p_molsum, p_wsum, deg, (float*)d_out);
}